// round 7
// baseline (speedup 1.0000x reference)
#include <cuda_runtime.h>
#include <math.h>
#include <float.h>

// Problem constants
#define NS 25      // support count (WAY*SHOT)
#define NQ 75      // query count (WAY*QUERY_SHOT)
#define DD 640     // feature dim
#define MM 25      // M (inner dim)

// Scratch (device globals)
__device__ float g_P[NQ * NS * DD];   // P[q][s][d] = sum_m S[s,d,m]*W[s,q,m]
__device__ float g_l2[NQ * NS];       // raw sum_d (p-r)^2, [q][s]
__device__ int   g_cnt[NQ];           // softmax tickets per q

// Packed fp32x2 FMA (Blackwell FFMA2; full fp32 precision, 2 lanes per op)
__device__ __forceinline__ unsigned long long ffma2(
        unsigned long long a, unsigned long long b, unsigned long long c) {
    unsigned long long d;
    asm("fma.rn.f32x2 %0, %1, %2, %3;" : "=l"(d) : "l"(a), "l"(b), "l"(c));
    return d;
}
#define UNPK_F32X2(lo, hi, v) \
    asm("mov.b64 {%0,%1}, %2;" : "=f"(lo), "=f"(hi) : "l"(v))

// ---------------------------------------------------------------------------
// Kernel 1: per-s GEMM. P[q][s][d] = sum_m W[s,q,m] * S[s,d,m]
// grid = (5 d-chunks of 128, 25 s), block = 480 (15 warps).
// Each warp: 5 q rows x 4 d. Inner loop uses FFMA2 on (d0,d1),(d2,d3) pairs;
// W staged duplicated as float2 so the broadcast needs one LDS.64, no pack.
// ---------------------------------------------------------------------------
__global__ __launch_bounds__(480) void k1_proj_support(
        const float* __restrict__ fm, const float* __restrict__ w2) {
    const int s  = blockIdx.y;
    const int d0 = blockIdx.x * 128;

    __shared__ __align__(16) float2 Wsm[MM][76];  // [m][q] duplicated (w,w)
    __shared__ __align__(16) float  Ssm[MM][132]; // [m][d], 128 d (+pad)

    const int tid = threadIdx.x;  // 480

    // Stage W[s,:,:] duplicated; incremental (q,m) tracking (480 = 19*25+5)
    {
        int q = tid / MM, m = tid - (tid / MM) * MM;
        for (int idx = tid; idx < NQ * MM; idx += 480) {
            float v = w2[s * (NQ * MM) + idx];
            Wsm[m][q] = make_float2(v, v);
            m += 5; q += 19;
            if (m >= MM) { m -= MM; q += 1; }
        }
    }
    // Stage S[s, d0:d0+128, :] -> Ssm[m][d]
    {
        int d = tid / MM, m = tid - (tid / MM) * MM;
        for (int idx = tid; idx < 128 * MM; idx += 480) {
            Ssm[m][d] = fm[s * (DD * MM) + d0 * MM + idx];
            m += 5; d += 19;
            if (m >= MM) { m -= MM; d += 1; }
        }
    }
    if (blockIdx.x == 0 && s == 0) {
        for (int i = tid; i < NQ * NS; i += 480) g_l2[i] = 0.0f;
        for (int i = tid; i < NQ; i += 480) g_cnt[i] = 0;
    }
    __syncthreads();

    const int lane = tid & 31;
    const int qb   = (tid >> 5) * 5;   // warp -> q base (0..70)

    unsigned long long acc01[5], acc23[5];
#pragma unroll
    for (int j = 0; j < 5; j++) { acc01[j] = 0ull; acc23[j] = 0ull; }

#pragma unroll
    for (int m = 0; m < MM; m++) {
        ulonglong2 bv = *reinterpret_cast<const ulonglong2*>(&Ssm[m][lane * 4]);
#pragma unroll
        for (int j = 0; j < 5; j++) {
            unsigned long long a =
                *reinterpret_cast<const unsigned long long*>(&Wsm[m][qb + j]);
            acc01[j] = ffma2(a, bv.x, acc01[j]);
            acc23[j] = ffma2(a, bv.y, acc23[j]);
        }
    }

#pragma unroll
    for (int j = 0; j < 5; j++) {
        float4 v;
        UNPK_F32X2(v.x, v.y, acc01[j]);
        UNPK_F32X2(v.z, v.w, acc23[j]);
        *reinterpret_cast<float4*>(
            &g_P[((qb + j) * NS + s) * DD + d0 + lane * 4]) = v;
    }
}

// ---------------------------------------------------------------------------
// Kernel 2: per-(q, d-chunk) GEMM + fused L2 atomics + last-block softmax.
// grid = (5 d-chunks of 128, 75 q), block = 448 (14 warps).
// Each warp owns 2 s rows; FFMA2 inner loop; P prefetched at block entry.
// ---------------------------------------------------------------------------
__global__ __launch_bounds__(448) void k2_query_acc_softmax(
        const float* __restrict__ fm, const float* __restrict__ w2,
        const float* __restrict__ scale, float* __restrict__ out) {
    const int q  = blockIdx.y;
    const int d0 = blockIdx.x * 128;

    __shared__ __align__(16) float2 Wsm[MM][33];  // [m][s] duplicated (w,w)
    __shared__ __align__(16) float  Qsm[MM][132]; // [m][d], 128 d (+pad)
    __shared__ int s_last;

    const int tid  = threadIdx.x;  // 448
    const int lane = tid & 31;
    const int warp = tid >> 5;     // 0..13
    const int sb   = warp * 2;     // s base (0..26)

    // Prefetch P for the epilogue (independent of the r-GEMM)
    float4 pv0 = make_float4(0.f, 0.f, 0.f, 0.f);
    float4 pv1 = make_float4(0.f, 0.f, 0.f, 0.f);
    if (sb < NS)
        pv0 = *reinterpret_cast<const float4*>(
            &g_P[(q * NS + sb) * DD + d0 + lane * 4]);
    if (sb + 1 < NS)
        pv1 = *reinterpret_cast<const float4*>(
            &g_P[(q * NS + sb + 1) * DD + d0 + lane * 4]);

    // Stage W[:,q,:] duplicated (625 elems, 2 passes of 448)
    for (int idx = tid; idx < NS * MM; idx += 448) {
        int sI = idx / MM, m = idx - sI * MM;
        float v = w2[(sI * NQ + q) * MM + m];
        Wsm[m][sI] = make_float2(v, v);
    }
    for (int idx = tid; idx < 8 * MM; idx += 448) {       // zero-pad s=25..32
        int m = idx % MM, sI = NS + idx / MM;
        Wsm[m][sI] = make_float2(0.f, 0.f);
    }
    // Stage Q[q, chunk, :] -> Qsm[m][d]; incremental (448 = 17*25+23)
    {
        int d = tid / MM, m = tid - (tid / MM) * MM;
        for (int idx = tid; idx < 128 * MM; idx += 448) {
            Qsm[m][d] = fm[(NS + q) * (DD * MM) + d0 * MM + idx];
            m += 23; d += 17;
            if (m >= MM) { m -= MM; d += 1; }
        }
    }
    __syncthreads();

    unsigned long long a01 = 0ull, a23 = 0ull;   // s = sb
    unsigned long long b01 = 0ull, b23 = 0ull;   // s = sb+1

#pragma unroll
    for (int m = 0; m < MM; m++) {
        ulonglong2 bv = *reinterpret_cast<const ulonglong2*>(&Qsm[m][lane * 4]);
        unsigned long long w0 =
            *reinterpret_cast<const unsigned long long*>(&Wsm[m][sb]);
        unsigned long long w1 =
            *reinterpret_cast<const unsigned long long*>(&Wsm[m][sb + 1]);
        a01 = ffma2(w0, bv.x, a01);
        a23 = ffma2(w0, bv.y, a23);
        b01 = ffma2(w1, bv.x, b01);
        b23 = ffma2(w1, bv.y, b23);
    }

    // Epilogue: (r - p)^2, lane reduce, atomic add
    {
        float r0, r1, r2, r3;
        UNPK_F32X2(r0, r1, a01);
        UNPK_F32X2(r2, r3, a23);
        float t0 = r0 - pv0.x, t1 = r1 - pv0.y;
        float t2 = r2 - pv0.z, t3 = r3 - pv0.w;
        float part = t0 * t0 + t1 * t1 + t2 * t2 + t3 * t3;
#pragma unroll
        for (int off = 16; off > 0; off >>= 1)
            part += __shfl_down_sync(0xffffffffu, part, off);
        if (lane == 0 && sb < NS)
            atomicAdd(&g_l2[q * NS + sb], part);
    }
    {
        float r0, r1, r2, r3;
        UNPK_F32X2(r0, r1, b01);
        UNPK_F32X2(r2, r3, b23);
        float t0 = r0 - pv1.x, t1 = r1 - pv1.y;
        float t2 = r2 - pv1.z, t3 = r3 - pv1.w;
        float part = t0 * t0 + t1 * t1 + t2 * t2 + t3 * t3;
#pragma unroll
        for (int off = 16; off > 0; off >>= 1)
            part += __shfl_down_sync(0xffffffffu, part, off);
        if (lane == 0 && sb + 1 < NS)
            atomicAdd(&g_l2[q * NS + sb + 1], part);
    }

    // Ticket: last of the 5 chunk-blocks for this q runs the softmax.
    __syncthreads();
    __threadfence();
    if (tid == 0)
        s_last = (atomicAdd(&g_cnt[q], 1) == 4) ? 1 : 0;
    __syncthreads();

    if (s_last && tid < 32) {
        __threadfence();  // acquire: other blocks' g_l2 adds visible
        const float c = -scale[0] / 312500.0f;  // 1/(M^2 * G*Q*Q*SHOT)
        float raw   = (tid < NS) ? __ldcg(&g_l2[q * NS + tid]) : 0.0f;
        float logit = (tid < NS) ? raw * c : -FLT_MAX;

        float mx = logit;
#pragma unroll
        for (int off = 16; off > 0; off >>= 1)
            mx = fmaxf(mx, __shfl_xor_sync(0xffffffffu, mx, off));

        float e = (tid < NS) ? expf(logit - mx) : 0.0f;
        float sum = e;
#pragma unroll
        for (int off = 16; off > 0; off >>= 1)
            sum += __shfl_xor_sync(0xffffffffu, sum, off);

        if (tid < NS)
            out[q * NS + tid] = logit - mx - logf(sum);
    }
}

// ---------------------------------------------------------------------------
extern "C" void kernel_launch(void* const* d_in, const int* in_sizes, int n_in,
                              void* d_out, int out_size) {
    const float* fm    = (const float*)d_in[0];  // (100, 640, 25) f32
    const float* w2    = (const float*)d_in[1];  // (25, 75, 25) f32
    const float* scale = (const float*)d_in[2];  // (1,) f32
    float* out = (float*)d_out;                  // (75, 25) f32

    k1_proj_support<<<dim3(5, 25), 480>>>(fm, w2);
    k2_query_acc_softmax<<<dim3(5, NQ), 448>>>(fm, w2, scale, out);
}

// round 8
// speedup vs baseline: 1.1385x; 1.1385x over previous
#include <cuda_runtime.h>
#include <math.h>
#include <float.h>

// Problem constants
#define NS 25      // support count (WAY*SHOT)
#define NQ 75      // query count (WAY*QUERY_SHOT)
#define DD 640     // feature dim
#define MM 25      // M (inner dim)

// Scratch (device globals)
__device__ float g_P[NQ * NS * DD];        // P[q][s][d] = sum_m S[s,d,m]*W[s,q,m]
__device__ float g_part[NQ * NS * 8];      // per-(q,s): 5 chunk partials (pad 8)

// ---------------------------------------------------------------------------
// Kernel 1: per-s GEMM. P[q][s][d] = sum_m W[s,q,m] * S[s,d,m]
// grid = (5 d-chunks of 128, 25 s), block = 480 (15 warps).
// Each warp: 5 q rows x 4 d (float4 per lane) -> covers q 0..74 exactly.
// ---------------------------------------------------------------------------
__global__ __launch_bounds__(480) void k1_proj_support(
        const float* __restrict__ fm, const float* __restrict__ w2) {
    const int s  = blockIdx.y;
    const int d0 = blockIdx.x * 128;

    __shared__ __align__(16) float Wsm[MM][76];   // [m][q], 75 q (+pad)
    __shared__ __align__(16) float Ssm[MM][132];  // [m][d], 128 d (+pad)

    const int tid = threadIdx.x;  // 480

    for (int idx = tid; idx < NQ * MM; idx += 480) {
        int q = idx / MM, m = idx - (idx / MM) * MM;
        Wsm[m][q] = w2[s * (NQ * MM) + idx];
    }
    for (int idx = tid; idx < 128 * MM; idx += 480) {
        int d = idx / MM, m = idx - (idx / MM) * MM;
        Ssm[m][d] = fm[s * (DD * MM) + d0 * MM + idx];
    }
    __syncthreads();

    const int lane = tid & 31;
    const int qb   = (tid >> 5) * 5;   // warp -> q base (0..70)

    float acc[5][4];
#pragma unroll
    for (int j = 0; j < 5; j++)
#pragma unroll
        for (int i = 0; i < 4; i++) acc[j][i] = 0.0f;

#pragma unroll
    for (int m = 0; m < MM; m++) {
        float4 bv = *reinterpret_cast<const float4*>(&Ssm[m][lane * 4]);
#pragma unroll
        for (int j = 0; j < 5; j++) {
            float a = Wsm[m][qb + j];
            acc[j][0] = fmaf(a, bv.x, acc[j][0]);
            acc[j][1] = fmaf(a, bv.y, acc[j][1]);
            acc[j][2] = fmaf(a, bv.z, acc[j][2]);
            acc[j][3] = fmaf(a, bv.w, acc[j][3]);
        }
    }

#pragma unroll
    for (int j = 0; j < 5; j++) {
        int q = qb + j;
        float4 v = make_float4(acc[j][0], acc[j][1], acc[j][2], acc[j][3]);
        *reinterpret_cast<float4*>(&g_P[(q * NS + s) * DD + d0 + lane * 4]) = v;
    }
}

// ---------------------------------------------------------------------------
// Kernel 2: per-(q, d-chunk) GEMM + partial L2 writeout. NO atomics/fences.
// grid = (5 d-chunks of 128, 75 q), block = 448 (14 warps).
// Each warp owns 2 s rows; lanes own 4 d (float4); P prefetched at entry.
// Block ends at a plain STG of its partial — minimal tail.
// ---------------------------------------------------------------------------
__global__ __launch_bounds__(448) void k2_query_partial(
        const float* __restrict__ fm, const float* __restrict__ w2) {
    const int q     = blockIdx.y;
    const int chunk = blockIdx.x;
    const int d0    = chunk * 128;

    __shared__ __align__(16) float Wsm[MM][36];   // [m][s], s padded to 32
    __shared__ __align__(16) float Qsm[MM][132];  // [m][d], 128 d (+pad)

    const int tid  = threadIdx.x;  // 448
    const int lane = tid & 31;
    const int warp = tid >> 5;     // 0..13
    const int sb   = warp * 2;     // s base (0..26), even

    // Prefetch P for the epilogue (independent of the r-GEMM)
    float4 pv0 = make_float4(0.f, 0.f, 0.f, 0.f);
    float4 pv1 = make_float4(0.f, 0.f, 0.f, 0.f);
    if (sb < NS)
        pv0 = *reinterpret_cast<const float4*>(
            &g_P[(q * NS + sb) * DD + d0 + lane * 4]);
    if (sb + 1 < NS)
        pv1 = *reinterpret_cast<const float4*>(
            &g_P[(q * NS + sb + 1) * DD + d0 + lane * 4]);

    // Stage W[:,q,:] and Q[q, chunk, :]
    for (int idx = tid; idx < NS * MM; idx += 448) {
        int sI = idx / MM, m = idx - (idx / MM) * MM;
        Wsm[m][sI] = w2[(sI * NQ + q) * MM + m];
    }
    for (int idx = tid; idx < 7 * MM; idx += 448) {       // zero-pad s=25..31
        int m = idx % MM, sI = NS + idx / MM;
        Wsm[m][sI] = 0.0f;
    }
    for (int idx = tid; idx < 128 * MM; idx += 448) {
        int d = idx / MM, m = idx - (idx / MM) * MM;
        Qsm[m][d] = fm[(NS + q) * (DD * MM) + d0 * MM + idx];
    }
    __syncthreads();

    float acc[2][4];
#pragma unroll
    for (int j = 0; j < 2; j++)
#pragma unroll
        for (int i = 0; i < 4; i++) acc[j][i] = 0.0f;

#pragma unroll
    for (int m = 0; m < MM; m++) {
        float4 bv = *reinterpret_cast<const float4*>(&Qsm[m][lane * 4]);
        float2 av = *reinterpret_cast<const float2*>(&Wsm[m][sb]);  // LDS.64
        acc[0][0] = fmaf(av.x, bv.x, acc[0][0]);
        acc[0][1] = fmaf(av.x, bv.y, acc[0][1]);
        acc[0][2] = fmaf(av.x, bv.z, acc[0][2]);
        acc[0][3] = fmaf(av.x, bv.w, acc[0][3]);
        acc[1][0] = fmaf(av.y, bv.x, acc[1][0]);
        acc[1][1] = fmaf(av.y, bv.y, acc[1][1]);
        acc[1][2] = fmaf(av.y, bv.z, acc[1][2]);
        acc[1][3] = fmaf(av.y, bv.w, acc[1][3]);
    }

    // Epilogue: (r - p)^2, lane reduce, plain STG of the partial. Done.
    {
        float t0 = acc[0][0] - pv0.x;
        float t1 = acc[0][1] - pv0.y;
        float t2 = acc[0][2] - pv0.z;
        float t3 = acc[0][3] - pv0.w;
        float part = t0 * t0 + t1 * t1 + t2 * t2 + t3 * t3;
#pragma unroll
        for (int off = 16; off > 0; off >>= 1)
            part += __shfl_down_sync(0xffffffffu, part, off);
        if (lane == 0 && sb < NS)
            g_part[(q * NS + sb) * 8 + chunk] = part;
    }
    {
        float t0 = acc[1][0] - pv1.x;
        float t1 = acc[1][1] - pv1.y;
        float t2 = acc[1][2] - pv1.z;
        float t3 = acc[1][3] - pv1.w;
        float part = t0 * t0 + t1 * t1 + t2 * t2 + t3 * t3;
#pragma unroll
        for (int off = 16; off > 0; off >>= 1)
            part += __shfl_down_sync(0xffffffffu, part, off);
        if (lane == 0 && sb + 1 < NS)
            g_part[(q * NS + sb + 1) * 8 + chunk] = part;
    }
}

// ---------------------------------------------------------------------------
// Kernel 3: sum 5 partials per (q,s), scale, log-softmax over s.
// grid = 75, block = 32 (one warp per query row).
// ---------------------------------------------------------------------------
__global__ void k3_softmax(const float* __restrict__ scale,
                           float* __restrict__ out) {
    const int q    = blockIdx.x;
    const int lane = threadIdx.x;

    const float c = -scale[0] / 312500.0f;  // 1/(M^2 * G*Q*Q*SHOT)

    float raw = 0.0f;
    if (lane < NS) {
        const float* p = &g_part[(q * NS + lane) * 8];
        float4 v = *reinterpret_cast<const float4*>(p);   // chunks 0..3
        raw = v.x + v.y + v.z + v.w + p[4];               // + chunk 4
    }
    float logit = (lane < NS) ? raw * c : -FLT_MAX;

    float mx = logit;
#pragma unroll
    for (int off = 16; off > 0; off >>= 1)
        mx = fmaxf(mx, __shfl_xor_sync(0xffffffffu, mx, off));

    float e = (lane < NS) ? expf(logit - mx) : 0.0f;
    float sum = e;
#pragma unroll
    for (int off = 16; off > 0; off >>= 1)
        sum += __shfl_xor_sync(0xffffffffu, sum, off);

    if (lane < NS)
        out[q * NS + lane] = logit - mx - logf(sum);
}

// ---------------------------------------------------------------------------
extern "C" void kernel_launch(void* const* d_in, const int* in_sizes, int n_in,
                              void* d_out, int out_size) {
    const float* fm    = (const float*)d_in[0];  // (100, 640, 25) f32
    const float* w2    = (const float*)d_in[1];  // (25, 75, 25) f32
    const float* scale = (const float*)d_in[2];  // (1,) f32
    float* out = (float*)d_out;                  // (75, 25) f32

    k1_proj_support<<<dim3(5, 25), 480>>>(fm, w2);
    k2_query_partial<<<dim3(5, NQ), 448>>>(fm, w2);
    k3_softmax<<<NQ, 32>>>(scale, out);
}